// round 1
// baseline (speedup 1.0000x reference)
#include <cuda_runtime.h>
#include <math_constants.h>

#define BATCH 16
#define NPTS  2048
#define KNN   10
#define NPAIRS 45
#define WPB   8                 // query points (warps) per block
#define THREADS (WPB * 32)

// scratch (no allocations allowed)
__device__ float g_loss[BATCH * NPTS];
__device__ float g_bmin[BATCH];

__constant__ int c_pa[NPAIRS] = {0,0,0,0,0,0,0,0,0, 1,1,1,1,1,1,1,1, 2,2,2,2,2,2,2,
                                 3,3,3,3,3,3, 4,4,4,4,4, 5,5,5,5, 6,6,6, 7,7, 8};
__constant__ int c_pb[NPAIRS] = {1,2,3,4,5,6,7,8,9, 2,3,4,5,6,7,8,9, 3,4,5,6,7,8,9,
                                 4,5,6,7,8,9, 5,6,7,8,9, 6,7,8,9, 7,8,9, 8,9, 9};

// direct |a-b|^2, non-fused, summed in reference order ((x+y)+z)
__device__ __forceinline__ float dist2_direct(float ax, float ay, float az,
                                              float bx, float by, float bz) {
    float dx = __fsub_rn(ax, bx), dy = __fsub_rn(ay, by), dz = __fsub_rn(az, bz);
    return __fadd_rn(__fadd_rn(__fmul_rn(dx, dx), __fmul_rn(dy, dy)), __fmul_rn(dz, dz));
}

__device__ __forceinline__ void sort3(float& a, float& b, float& c) {
    if (a > b) { float t = a; a = b; b = t; }
    if (b > c) { float t = b; b = c; c = t; }
    if (a > b) { float t = a; a = b; b = t; }
}

__global__ __launch_bounds__(THREADS)
void knn_loss_kernel(const float* __restrict__ src, const float* __restrict__ tgt) {
    __shared__ float sx[NPTS], sy[NPTS], sz[NPTS], ssq[NPTS];
    __shared__ int   s_id[WPB][KNN];
    __shared__ float s_sp[WPB][11][3];   // [0]=self, [1..10]=neighbors (src)
    __shared__ float s_tp[WPB][11][3];   // same for tgt

    const int b  = blockIdx.x / (NPTS / WPB);
    const int i0 = (blockIdx.x % (NPTS / WPB)) * WPB;
    const float* sb = src + (size_t)b * 3 * NPTS;
    const float* tb = tgt + (size_t)b * 3 * NPTS;

    for (int j = threadIdx.x; j < NPTS; j += THREADS) {
        float x = sb[j], y = sb[NPTS + j], z = sb[2 * NPTS + j];
        sx[j] = x; sy[j] = y; sz[j] = z;
        ssq[j] = __fadd_rn(__fadd_rn(__fmul_rn(x, x), __fmul_rn(y, y)), __fmul_rn(z, z));
    }
    __syncthreads();

    const int w = threadIdx.x >> 5, lane = threadIdx.x & 31;
    const int i = i0 + w;
    const float xi = sx[i], yi = sy[i], zi = sz[i], sqi = ssq[i];

    // per-lane sorted top-10 (ascending d2), index tie-break = smaller index
    float d[KNN]; int id[KNN];
#pragma unroll
    for (int k = 0; k < KNN; k++) { d[k] = CUDART_INF_F; id[k] = 0x7FFFFFFF; }

    for (int j = lane; j < NPTS; j += 32) {
        // replicate reference: d2 = (sq_i + sq_j) - 2*dot  (expansion form)
        float dot = __fadd_rn(__fadd_rn(__fmul_rn(xi, sx[j]), __fmul_rn(yi, sy[j])),
                              __fmul_rn(zi, sz[j]));
        float d2  = __fsub_rn(__fadd_rn(sqi, ssq[j]), __fmul_rn(2.0f, dot));
        float dist = -__fadd_rn(d2, 1e-7f);
        if (dist > -0.1f) continue;        // masked (too close / self)
        if (d2 < d[KNN - 1]) {
            d[KNN - 1] = d2; id[KNN - 1] = j;
#pragma unroll
            for (int k = KNN - 1; k > 0; k--) {
                if (d[k] < d[k - 1]) {
                    float td = d[k]; d[k] = d[k - 1]; d[k - 1] = td;
                    int   ti = id[k]; id[k] = id[k - 1]; id[k - 1] = ti;
                }
            }
        }
    }

    // 10 warp-argmin extraction rounds (stable: value then index, matches top_k)
#pragma unroll
    for (int r = 0; r < KNN; r++) {
        float v = d[0]; int vid = id[0];
#pragma unroll
        for (int off = 16; off; off >>= 1) {
            float ov = __shfl_xor_sync(0xFFFFFFFFu, v, off);
            int  oid = __shfl_xor_sync(0xFFFFFFFFu, vid, off);
            if (ov < v || (ov == v && oid < vid)) { v = ov; vid = oid; }
        }
        if (lane == 0) s_id[w][r] = vid;
        if (id[0] == vid) {                 // winner pops (ids are unique)
#pragma unroll
            for (int k = 0; k < KNN - 1; k++) { d[k] = d[k + 1]; id[k] = id[k + 1]; }
            d[KNN - 1] = CUDART_INF_F; id[KNN - 1] = 0x7FFFFFFF;
        }
    }
    __syncwarp();

    // stage the 11 relevant src/tgt points for this query
    if (lane < 11) {
        int gj = (lane == 0) ? i : s_id[w][lane - 1];
        s_sp[w][lane][0] = sx[gj]; s_sp[w][lane][1] = sy[gj]; s_sp[w][lane][2] = sz[gj];
        s_tp[w][lane][0] = tb[gj]; s_tp[w][lane][1] = tb[NPTS + gj]; s_tp[w][lane][2] = tb[2 * NPTS + gj];
    }
    __syncwarp();

    // 45 pair-losses, <=2 per lane
    float l0 = CUDART_INF_F, l1 = CUDART_INF_F;
#pragma unroll
    for (int half = 0; half < 2; half++) {
        int t = lane + 32 * half;
        if (t < NPAIRS) {
            int a = c_pa[t] + 1, c = c_pb[t] + 1;   // indices into staged 11-point arrays
            // src triangle sides (direct formula, like get_tri)
            float s01 = dist2_direct(s_sp[w][0][0], s_sp[w][0][1], s_sp[w][0][2],
                                     s_sp[w][a][0], s_sp[w][a][1], s_sp[w][a][2]);
            float s12 = dist2_direct(s_sp[w][a][0], s_sp[w][a][1], s_sp[w][a][2],
                                     s_sp[w][c][0], s_sp[w][c][1], s_sp[w][c][2]);
            float s02 = dist2_direct(s_sp[w][0][0], s_sp[w][0][1], s_sp[w][0][2],
                                     s_sp[w][c][0], s_sp[w][c][1], s_sp[w][c][2]);
            sort3(s01, s12, s02);
            float t01 = dist2_direct(s_tp[w][0][0], s_tp[w][0][1], s_tp[w][0][2],
                                     s_tp[w][a][0], s_tp[w][a][1], s_tp[w][a][2]);
            float t12 = dist2_direct(s_tp[w][a][0], s_tp[w][a][1], s_tp[w][a][2],
                                     s_tp[w][c][0], s_tp[w][c][1], s_tp[w][c][2]);
            float t02 = dist2_direct(s_tp[w][0][0], s_tp[w][0][1], s_tp[w][0][2],
                                     s_tp[w][c][0], s_tp[w][c][1], s_tp[w][c][2]);
            sort3(t01, t12, t02);
            t01 = __fadd_rn(t01, 1e-6f);   // EPS added after sort
            t12 = __fadd_rn(t12, 1e-6f);
            t02 = __fadd_rn(t02, 1e-6f);
            float q0 = __fsub_rn(s01, t01), q1 = __fsub_rn(s12, t12), q2 = __fsub_rn(s02, t02);
            float p0 = __fadd_rn(s01, t01), p1 = __fadd_rn(s12, t12), p2 = __fadd_rn(s02, t02);
            float num = __fadd_rn(__fadd_rn(__fmul_rn(q0, q0), __fmul_rn(q1, q1)), __fmul_rn(q2, q2));
            float den = __fadd_rn(__fadd_rn(__fmul_rn(p0, p0), __fmul_rn(p1, p1)), __fmul_rn(p2, p2));
            float ls = __fdiv_rn(num, den);
            if (half == 0) l0 = ls; else l1 = ls;
        }
    }

    // extract 10 smallest of 45 in ascending order, accumulate sqrt(l+eps)
    float lo = fminf(l0, l1), hi = fmaxf(l0, l1);
    float acc = 0.0f;
#pragma unroll
    for (int r = 0; r < KNN; r++) {
        float v = lo; int wl = lane;
#pragma unroll
        for (int off = 16; off; off >>= 1) {
            float ov = __shfl_xor_sync(0xFFFFFFFFu, v, off);
            int  owl = __shfl_xor_sync(0xFFFFFFFFu, wl, off);
            if (ov < v || (ov == v && owl < wl)) { v = ov; wl = owl; }
        }
        acc = __fadd_rn(acc, __fsqrt_rn(__fadd_rn(v, 1e-6f)));
        if (lane == wl) { lo = hi; hi = CUDART_INF_F; }
    }
    if (lane == 0) g_loss[b * NPTS + i] = __fdiv_rn(acc, 10.0f);
}

__global__ void min_kernel() {
    __shared__ float red[256];
    const int b = blockIdx.x;
    float m = CUDART_INF_F;
    for (int j = threadIdx.x; j < NPTS; j += 256) m = fminf(m, g_loss[b * NPTS + j]);
    red[threadIdx.x] = m;
    __syncthreads();
    for (int s = 128; s; s >>= 1) {
        if (threadIdx.x < s) red[threadIdx.x] = fminf(red[threadIdx.x], red[threadIdx.x + s]);
        __syncthreads();
    }
    if (threadIdx.x == 0) g_bmin[b] = red[0];
}

__global__ void weight_kernel(float* __restrict__ out) {
    int idx = blockIdx.x * 256 + threadIdx.x;
    if (idx < BATCH * NPTS) {
        int b = idx >> 11;
        float dl = __fsub_rn(g_loss[idx], g_bmin[b]);
        // weight = 2*sigmoid(-30*dl) = 2 / (1 + exp(30*dl))
        float wgt = __fdiv_rn(2.0f, __fadd_rn(1.0f, expf(__fmul_rn(30.0f, dl))));
        out[idx] = (wgt > 0.6f) ? 1.0f : 0.0f;
    }
}

extern "C" void kernel_launch(void* const* d_in, const int* in_sizes, int n_in,
                              void* d_out, int out_size) {
    const float* src = (const float*)d_in[0];
    const float* tgt = (const float*)d_in[1];
    float* out = (float*)d_out;
    knn_loss_kernel<<<BATCH * NPTS / WPB, THREADS>>>(src, tgt);
    min_kernel<<<BATCH, 256>>>();
    weight_kernel<<<(BATCH * NPTS + 255) / 256, 256>>>(out);
}

// round 2
// speedup vs baseline: 2.2411x; 2.2411x over previous
#include <cuda_runtime.h>
#include <math_constants.h>

#define BATCH 16
#define NPTS  2048
#define KNN   10
#define NPAIRS 45
#define WPB   8                 // query points (warps) per block
#define THREADS (WPB * 32)
#define FULLMASK 0xFFFFFFFFu

// scratch (no allocations allowed)
__device__ float g_loss[BATCH * NPTS];
__device__ float g_bmin[BATCH];

__constant__ int c_pa[NPAIRS] = {0,0,0,0,0,0,0,0,0, 1,1,1,1,1,1,1,1, 2,2,2,2,2,2,2,
                                 3,3,3,3,3,3, 4,4,4,4,4, 5,5,5,5, 6,6,6, 7,7, 8};
__constant__ int c_pb[NPAIRS] = {1,2,3,4,5,6,7,8,9, 2,3,4,5,6,7,8,9, 3,4,5,6,7,8,9,
                                 4,5,6,7,8,9, 5,6,7,8,9, 6,7,8,9, 7,8,9, 8,9, 9};

// direct |a-b|^2, non-fused, summed in reference order ((x+y)+z)
__device__ __forceinline__ float dist2_direct(float ax, float ay, float az,
                                              float bx, float by, float bz) {
    float dx = __fsub_rn(ax, bx), dy = __fsub_rn(ay, by), dz = __fsub_rn(az, bz);
    return __fadd_rn(__fadd_rn(__fmul_rn(dx, dx), __fmul_rn(dy, dy)), __fmul_rn(dz, dz));
}

__device__ __forceinline__ void sort3(float& a, float& b, float& c) {
    if (a > b) { float t = a; a = b; b = t; }
    if (b > c) { float t = b; b = c; c = t; }
    if (a > b) { float t = a; a = b; b = t; }
}

__global__ __launch_bounds__(THREADS)
void knn_loss_kernel(const float* __restrict__ src, const float* __restrict__ tgt) {
    __shared__ float4 spt[NPTS];         // x, y, z, |p|^2
    __shared__ int   s_id[WPB][KNN];
    __shared__ float s_sp[WPB][11][3];   // [0]=self, [1..10]=neighbors (src)
    __shared__ float s_tp[WPB][11][3];   // same for tgt

    const int b  = blockIdx.x / (NPTS / WPB);
    const int i0 = (blockIdx.x % (NPTS / WPB)) * WPB;
    const float* sb = src + (size_t)b * 3 * NPTS;
    const float* tb = tgt + (size_t)b * 3 * NPTS;

    for (int j = threadIdx.x; j < NPTS; j += THREADS) {
        float x = sb[j], y = sb[NPTS + j], z = sb[2 * NPTS + j];
        float sq = __fadd_rn(__fadd_rn(__fmul_rn(x, x), __fmul_rn(y, y)), __fmul_rn(z, z));
        spt[j] = make_float4(x, y, z, sq);
    }
    __syncthreads();

    const int w = threadIdx.x >> 5, lane = threadIdx.x & 31;
    const int i = i0 + w;
    const float4 qi = spt[i];
    const float xi = qi.x, yi = qi.y, zi = qi.z, sqi = qi.w;

    // warp-global sorted top-10 in lanes 0..9 (ascending key nd = d2 + 1e-7)
    float dtop = CUDART_INF_F;
    int   itop = 0x7FFFFFFF;
    float tau  = CUDART_INF_F;           // current 10th-smallest (lane 9's dtop)

#pragma unroll 4
    for (int t = 0; t < NPTS / 32; t++) {
        const int j = t * 32 + lane;
        float4 c = spt[j];
        // replicate reference: d2 = (sq_i + sq_j) - 2*dot  (expansion form)
        float dot = __fadd_rn(__fadd_rn(__fmul_rn(xi, c.x), __fmul_rn(yi, c.y)),
                              __fmul_rn(zi, c.z));
        float d2  = __fsub_rn(__fadd_rn(sqi, c.w), __fmul_rn(2.0f, dot));
        float nd  = __fadd_rn(d2, 1e-7f);      // reference sort key (negated distance)
        // masked iff nd < 0.1 ; accept iff survives mask AND beats global 10th
        bool accept = (nd >= 0.1f) && (nd < tau);
        unsigned acc = __ballot_sync(FULLMASK, accept);
        if (acc) {
            do {
                int srcl = __ffs(acc) - 1;
                acc &= acc - 1;
                float v  = __shfl_sync(FULLMASK, nd, srcl);
                int   vj = t * 32 + srcl;
                // insertion position: # of kept entries <= v (stable: equals stay first)
                unsigned ble = __ballot_sync(FULLMASK, dtop <= v) & 0x3FFu;
                int pos = __popc(ble);
                float dprev = __shfl_up_sync(FULLMASK, dtop, 1);
                int   iprev = __shfl_up_sync(FULLMASK, itop, 1);
                if (lane < KNN) {
                    if (lane == pos)      { dtop = v;     itop = vj;    }
                    else if (lane > pos)  { dtop = dprev; itop = iprev; }
                }
            } while (acc);
            tau = __shfl_sync(FULLMASK, dtop, KNN - 1);
        }
    }

    if (lane < KNN) s_id[w][lane] = itop;
    __syncwarp();

    // stage the 11 relevant src/tgt points for this query
    if (lane < 11) {
        int gj = (lane == 0) ? i : s_id[w][lane - 1];
        float4 p = spt[gj];
        s_sp[w][lane][0] = p.x; s_sp[w][lane][1] = p.y; s_sp[w][lane][2] = p.z;
        s_tp[w][lane][0] = tb[gj]; s_tp[w][lane][1] = tb[NPTS + gj]; s_tp[w][lane][2] = tb[2 * NPTS + gj];
    }
    __syncwarp();

    // 45 pair-losses, <=2 per lane
    float l0 = CUDART_INF_F, l1 = CUDART_INF_F;
#pragma unroll
    for (int half = 0; half < 2; half++) {
        int t = lane + 32 * half;
        if (t < NPAIRS) {
            int a = c_pa[t] + 1, c = c_pb[t] + 1;   // indices into staged 11-point arrays
            float s01 = dist2_direct(s_sp[w][0][0], s_sp[w][0][1], s_sp[w][0][2],
                                     s_sp[w][a][0], s_sp[w][a][1], s_sp[w][a][2]);
            float s12 = dist2_direct(s_sp[w][a][0], s_sp[w][a][1], s_sp[w][a][2],
                                     s_sp[w][c][0], s_sp[w][c][1], s_sp[w][c][2]);
            float s02 = dist2_direct(s_sp[w][0][0], s_sp[w][0][1], s_sp[w][0][2],
                                     s_sp[w][c][0], s_sp[w][c][1], s_sp[w][c][2]);
            sort3(s01, s12, s02);
            float t01 = dist2_direct(s_tp[w][0][0], s_tp[w][0][1], s_tp[w][0][2],
                                     s_tp[w][a][0], s_tp[w][a][1], s_tp[w][a][2]);
            float t12 = dist2_direct(s_tp[w][a][0], s_tp[w][a][1], s_tp[w][a][2],
                                     s_tp[w][c][0], s_tp[w][c][1], s_tp[w][c][2]);
            float t02 = dist2_direct(s_tp[w][0][0], s_tp[w][0][1], s_tp[w][0][2],
                                     s_tp[w][c][0], s_tp[w][c][1], s_tp[w][c][2]);
            sort3(t01, t12, t02);
            t01 = __fadd_rn(t01, 1e-6f);   // EPS added after sort
            t12 = __fadd_rn(t12, 1e-6f);
            t02 = __fadd_rn(t02, 1e-6f);
            float q0 = __fsub_rn(s01, t01), q1 = __fsub_rn(s12, t12), q2 = __fsub_rn(s02, t02);
            float p0 = __fadd_rn(s01, t01), p1 = __fadd_rn(s12, t12), p2 = __fadd_rn(s02, t02);
            float num = __fadd_rn(__fadd_rn(__fmul_rn(q0, q0), __fmul_rn(q1, q1)), __fmul_rn(q2, q2));
            float den = __fadd_rn(__fadd_rn(__fmul_rn(p0, p0), __fmul_rn(p1, p1)), __fmul_rn(p2, p2));
            float ls = __fdiv_rn(num, den);
            if (half == 0) l0 = ls; else l1 = ls;
        }
    }

    // extract 10 smallest of 45 in ascending order, accumulate sqrt(l+eps)
    float lo = fminf(l0, l1), hi = fmaxf(l0, l1);
    float acc = 0.0f;
#pragma unroll
    for (int r = 0; r < KNN; r++) {
        float v = lo; int wl = lane;
#pragma unroll
        for (int off = 16; off; off >>= 1) {
            float ov = __shfl_xor_sync(FULLMASK, v, off);
            int  owl = __shfl_xor_sync(FULLMASK, wl, off);
            if (ov < v || (ov == v && owl < wl)) { v = ov; wl = owl; }
        }
        acc = __fadd_rn(acc, __fsqrt_rn(__fadd_rn(v, 1e-6f)));
        if (lane == wl) { lo = hi; hi = CUDART_INF_F; }
    }
    if (lane == 0) g_loss[b * NPTS + i] = __fdiv_rn(acc, 10.0f);
}

__global__ void min_kernel() {
    __shared__ float red[256];
    const int b = blockIdx.x;
    float m = CUDART_INF_F;
    for (int j = threadIdx.x; j < NPTS; j += 256) m = fminf(m, g_loss[b * NPTS + j]);
    red[threadIdx.x] = m;
    __syncthreads();
    for (int s = 128; s; s >>= 1) {
        if (threadIdx.x < s) red[threadIdx.x] = fminf(red[threadIdx.x], red[threadIdx.x + s]);
        __syncthreads();
    }
    if (threadIdx.x == 0) g_bmin[b] = red[0];
}

__global__ void weight_kernel(float* __restrict__ out) {
    int idx = blockIdx.x * 256 + threadIdx.x;
    if (idx < BATCH * NPTS) {
        int b = idx >> 11;
        float dl = __fsub_rn(g_loss[idx], g_bmin[b]);
        // weight = 2*sigmoid(-30*dl) = 2 / (1 + exp(30*dl))
        float wgt = __fdiv_rn(2.0f, __fadd_rn(1.0f, expf(__fmul_rn(30.0f, dl))));
        out[idx] = (wgt > 0.6f) ? 1.0f : 0.0f;
    }
}

extern "C" void kernel_launch(void* const* d_in, const int* in_sizes, int n_in,
                              void* d_out, int out_size) {
    const float* src = (const float*)d_in[0];
    const float* tgt = (const float*)d_in[1];
    float* out = (float*)d_out;
    knn_loss_kernel<<<BATCH * NPTS / WPB, THREADS>>>(src, tgt);
    min_kernel<<<BATCH, 256>>>();
    weight_kernel<<<(BATCH * NPTS + 255) / 256, 256>>>(out);
}

// round 3
// speedup vs baseline: 2.9355x; 1.3099x over previous
#include <cuda_runtime.h>
#include <math_constants.h>

#define BATCH 16
#define NPTS  2048
#define KNN   10
#define NPAIRS 45
#define WPB   16                // query points (warps) per block
#define THREADS (WPB * 32)
#define FULLMASK 0xFFFFFFFFu

// scratch (no allocations allowed)
__device__ float g_loss[BATCH * NPTS];
__device__ float g_bmin[BATCH];

__constant__ int c_pa[NPAIRS] = {0,0,0,0,0,0,0,0,0, 1,1,1,1,1,1,1,1, 2,2,2,2,2,2,2,
                                 3,3,3,3,3,3, 4,4,4,4,4, 5,5,5,5, 6,6,6, 7,7, 8};
__constant__ int c_pb[NPAIRS] = {1,2,3,4,5,6,7,8,9, 2,3,4,5,6,7,8,9, 3,4,5,6,7,8,9,
                                 4,5,6,7,8,9, 5,6,7,8,9, 6,7,8,9, 7,8,9, 8,9, 9};

// direct |a-b|^2, non-fused, summed in reference order ((x+y)+z)
__device__ __forceinline__ float dist2_direct(float ax, float ay, float az,
                                              float bx, float by, float bz) {
    float dx = __fsub_rn(ax, bx), dy = __fsub_rn(ay, by), dz = __fsub_rn(az, bz);
    return __fadd_rn(__fadd_rn(__fmul_rn(dx, dx), __fmul_rn(dy, dy)), __fmul_rn(dz, dz));
}

__device__ __forceinline__ void sort3(float& a, float& b, float& c) {
    if (a > b) { float t = a; a = b; b = t; }
    if (b > c) { float t = b; b = c; c = t; }
    if (a > b) { float t = a; a = b; b = t; }
}

__global__ __launch_bounds__(THREADS, 4)
void knn_loss_kernel(const float* __restrict__ src, const float* __restrict__ tgt) {
    // spt holds (2x, 2y, 2z, |p|^2): pre-doubled coords make rn(xi*2cx)+... equal
    // EXACTLY 2*dot of the reference (scaling by 2 is exact and commutes with rn).
    __shared__ float4 spt[NPTS];
    __shared__ int   s_id[WPB][KNN];
    __shared__ float s_sp[WPB][11][3];   // [0]=self, [1..10]=neighbors (src)
    __shared__ float s_tp[WPB][11][3];   // same for tgt

    const int b  = blockIdx.x / (NPTS / WPB);
    const int i0 = (blockIdx.x % (NPTS / WPB)) * WPB;
    const float* sb = src + (size_t)b * 3 * NPTS;
    const float* tb = tgt + (size_t)b * 3 * NPTS;

    for (int j = threadIdx.x; j < NPTS; j += THREADS) {
        float x = sb[j], y = sb[NPTS + j], z = sb[2 * NPTS + j];
        float sq = __fadd_rn(__fadd_rn(__fmul_rn(x, x), __fmul_rn(y, y)), __fmul_rn(z, z));
        spt[j] = make_float4(2.0f * x, 2.0f * y, 2.0f * z, sq);
    }
    __syncthreads();

    const int w = threadIdx.x >> 5, lane = threadIdx.x & 31;
    const int i = i0 + w;
    const float4 qi = spt[i];
    const float xi = 0.5f * qi.x, yi = 0.5f * qi.y, zi = 0.5f * qi.z, sqi = qi.w;

    // warp-global sorted top-10 in lanes 0..9 (ascending key nd = d2 + 1e-7)
    float dtop;
    int   itop;
    float tau;

    // ---- tile 0 (j = lane): bitonic init of the sorted list ----
    {
        float4 c = spt[lane];
        float dot2 = __fadd_rn(__fadd_rn(__fmul_rn(xi, c.x), __fmul_rn(yi, c.y)),
                               __fmul_rn(zi, c.z));            // == 2*dot exactly
        float d2  = __fsub_rn(__fadd_rn(sqi, c.w), dot2);
        float nd  = __fadd_rn(d2, 1e-7f);
        float key = (nd < 0.1f) ? CUDART_INF_F : nd;           // masked -> +inf
        int   idx = lane;
#pragma unroll
        for (int k = 2; k <= 32; k <<= 1) {
#pragma unroll
            for (int s = k >> 1; s > 0; s >>= 1) {
                float okey = __shfl_xor_sync(FULLMASK, key, s);
                int   oidx = __shfl_xor_sync(FULLMASK, idx, s);
                bool up   = ((lane & k) == 0);
                bool low  = ((lane & s) == 0);
                bool takeSmaller = (low == up);
                bool otherSmaller = (okey < key) || (okey == key && oidx < idx);
                bool take = takeSmaller ? otherSmaller : !otherSmaller;
                if (take) { key = okey; idx = oidx; }
            }
        }
        dtop = key; itop = idx;            // lanes 0..9 = top-10 ascending, idx tie-break
        tau  = __shfl_sync(FULLMASK, dtop, KNN - 1);
    }

    // ---- tiles 1..63: threshold scan + rare serialized inserts ----
#pragma unroll 4
    for (int t = 1; t < NPTS / 32; t++) {
        const int j = t * 32 + lane;
        float4 c = spt[j];
        float dot2 = __fadd_rn(__fadd_rn(__fmul_rn(xi, c.x), __fmul_rn(yi, c.y)),
                               __fmul_rn(zi, c.z));
        float d2  = __fsub_rn(__fadd_rn(sqi, c.w), dot2);
        float nd  = __fadd_rn(d2, 1e-7f);
        bool accept = (nd >= 0.1f) && (nd < tau);
        unsigned acc = __ballot_sync(FULLMASK, accept);
        if (acc) {
            do {
                int srcl = __ffs(acc) - 1;
                acc &= acc - 1;
                float v  = __shfl_sync(FULLMASK, nd, srcl);
                int   vj = t * 32 + srcl;
                // insertion position: # of kept entries <= v (stable: equals stay first)
                unsigned ble = __ballot_sync(FULLMASK, dtop <= v) & 0x3FFu;
                int pos = __popc(ble);
                float dprev = __shfl_up_sync(FULLMASK, dtop, 1);
                int   iprev = __shfl_up_sync(FULLMASK, itop, 1);
                if (lane < KNN) {
                    if (lane == pos)      { dtop = v;     itop = vj;    }
                    else if (lane > pos)  { dtop = dprev; itop = iprev; }
                }
            } while (acc);
            tau = __shfl_sync(FULLMASK, dtop, KNN - 1);
        }
    }

    if (lane < KNN) s_id[w][lane] = itop;
    __syncwarp();

    // stage the 11 relevant src/tgt points for this query
    if (lane < 11) {
        int gj = (lane == 0) ? i : s_id[w][lane - 1];
        float4 p = spt[gj];
        s_sp[w][lane][0] = 0.5f * p.x; s_sp[w][lane][1] = 0.5f * p.y; s_sp[w][lane][2] = 0.5f * p.z;
        s_tp[w][lane][0] = tb[gj]; s_tp[w][lane][1] = tb[NPTS + gj]; s_tp[w][lane][2] = tb[2 * NPTS + gj];
    }
    __syncwarp();

    // 45 pair-losses, <=2 per lane
    float l0 = CUDART_INF_F, l1 = CUDART_INF_F;
#pragma unroll
    for (int half = 0; half < 2; half++) {
        int t = lane + 32 * half;
        if (t < NPAIRS) {
            int a = c_pa[t] + 1, c = c_pb[t] + 1;   // indices into staged 11-point arrays
            float s01 = dist2_direct(s_sp[w][0][0], s_sp[w][0][1], s_sp[w][0][2],
                                     s_sp[w][a][0], s_sp[w][a][1], s_sp[w][a][2]);
            float s12 = dist2_direct(s_sp[w][a][0], s_sp[w][a][1], s_sp[w][a][2],
                                     s_sp[w][c][0], s_sp[w][c][1], s_sp[w][c][2]);
            float s02 = dist2_direct(s_sp[w][0][0], s_sp[w][0][1], s_sp[w][0][2],
                                     s_sp[w][c][0], s_sp[w][c][1], s_sp[w][c][2]);
            sort3(s01, s12, s02);
            float t01 = dist2_direct(s_tp[w][0][0], s_tp[w][0][1], s_tp[w][0][2],
                                     s_tp[w][a][0], s_tp[w][a][1], s_tp[w][a][2]);
            float t12 = dist2_direct(s_tp[w][a][0], s_tp[w][a][1], s_tp[w][a][2],
                                     s_tp[w][c][0], s_tp[w][c][1], s_tp[w][c][2]);
            float t02 = dist2_direct(s_tp[w][0][0], s_tp[w][0][1], s_tp[w][0][2],
                                     s_tp[w][c][0], s_tp[w][c][1], s_tp[w][c][2]);
            sort3(t01, t12, t02);
            t01 = __fadd_rn(t01, 1e-6f);   // EPS added after sort
            t12 = __fadd_rn(t12, 1e-6f);
            t02 = __fadd_rn(t02, 1e-6f);
            float q0 = __fsub_rn(s01, t01), q1 = __fsub_rn(s12, t12), q2 = __fsub_rn(s02, t02);
            float p0 = __fadd_rn(s01, t01), p1 = __fadd_rn(s12, t12), p2 = __fadd_rn(s02, t02);
            float num = __fadd_rn(__fadd_rn(__fmul_rn(q0, q0), __fmul_rn(q1, q1)), __fmul_rn(q2, q2));
            float den = __fadd_rn(__fadd_rn(__fmul_rn(p0, p0), __fmul_rn(p1, p1)), __fmul_rn(p2, p2));
            float ls = __fdiv_rn(num, den);
            if (half == 0) l0 = ls; else l1 = ls;
        }
    }

    // extract 10 smallest of 45 ascending; sum sqrt(l+eps) in that order
    float lo = fminf(l0, l1), hi = fmaxf(l0, l1);
    float acc = 0.0f;
#pragma unroll
    for (int r = 0; r < KNN; r++) {
        float v = lo;
#pragma unroll
        for (int off = 16; off; off >>= 1)
            v = fminf(v, __shfl_xor_sync(FULLMASK, v, off));
        unsigned m = __ballot_sync(FULLMASK, lo == v);
        int win = __ffs(m) - 1;
        acc = __fadd_rn(acc, __fsqrt_rn(__fadd_rn(v, 1e-6f)));
        if (lane == win) { lo = hi; hi = CUDART_INF_F; }
    }
    if (lane == 0) g_loss[b * NPTS + i] = __fdiv_rn(acc, 10.0f);
}

__global__ void min_kernel() {
    __shared__ float red[256];
    const int b = blockIdx.x;
    float m = CUDART_INF_F;
    for (int j = threadIdx.x; j < NPTS; j += 256) m = fminf(m, g_loss[b * NPTS + j]);
    red[threadIdx.x] = m;
    __syncthreads();
    for (int s = 128; s; s >>= 1) {
        if (threadIdx.x < s) red[threadIdx.x] = fminf(red[threadIdx.x], red[threadIdx.x + s]);
        __syncthreads();
    }
    if (threadIdx.x == 0) g_bmin[b] = red[0];
}

__global__ void weight_kernel(float* __restrict__ out) {
    int idx = blockIdx.x * 256 + threadIdx.x;
    if (idx < BATCH * NPTS) {
        int b = idx >> 11;
        float dl = __fsub_rn(g_loss[idx], g_bmin[b]);
        // weight = 2*sigmoid(-30*dl) = 2 / (1 + exp(30*dl))
        float wgt = __fdiv_rn(2.0f, __fadd_rn(1.0f, expf(__fmul_rn(30.0f, dl))));
        out[idx] = (wgt > 0.6f) ? 1.0f : 0.0f;
    }
}

extern "C" void kernel_launch(void* const* d_in, const int* in_sizes, int n_in,
                              void* d_out, int out_size) {
    const float* src = (const float*)d_in[0];
    const float* tgt = (const float*)d_in[1];
    float* out = (float*)d_out;
    knn_loss_kernel<<<BATCH * NPTS / WPB, THREADS>>>(src, tgt);
    min_kernel<<<BATCH, 256>>>();
    weight_kernel<<<(BATCH * NPTS + 255) / 256, 256>>>(out);
}